// round 3
// baseline (speedup 1.0000x reference)
#include <cuda_runtime.h>

#define DM   1024
#define NH   16
#define DK   64
#define BATCH 32
#define SEQ  512
#define MTOK (BATCH*SEQ)   // 16384
#define EPSV 1e-6f

// -------- scratch (static __device__, no runtime allocation) --------
__device__ float g_qf[(size_t)MTOK * DM];   // phi(Q), head-major [B,H,N,Dk]
__device__ float g_kf[(size_t)MTOK * DM];   // phi(K), head-major
__device__ float g_v [(size_t)MTOK * DM];   // V, head-major
__device__ float g_at[(size_t)MTOK * DM];   // attention out, token-major [B,N,H,Dk]
__device__ float g_kv[(size_t)BATCH * NH * DK * DK];
__device__ float g_ks[(size_t)BATCH * NH * DK];

// ---------------------------------------------------------------
// 128x128x8 fp32 SGEMM tile: C[m0:m0+128, n0:n0+128] = A[M,1024] @ W[1024,1024]
// 256 threads, each an 8x8 micro-tile. acc must be zero-initialized by caller.
// ---------------------------------------------------------------
__device__ __forceinline__ void sgemm_tile(
    const float* __restrict__ A, const float* __restrict__ W,
    int m0, int n0, float acc[8][8], float* As, float* Bs)
{
    const int tid   = threadIdx.x;
    const int aRow  = tid >> 1;          // 0..127
    const int aHalf = tid & 1;           // 0..1
    const int bRow  = tid >> 5;          // 0..7
    const int bCol  = (tid & 31) << 2;   // 0..124 step 4
    const int ty    = tid >> 4;          // 0..15
    const int tx    = tid & 15;          // 0..15

    for (int k0 = 0; k0 < DM; k0 += 8) {
        __syncthreads();
        // A tile 128x8 -> As[k][m] (transposed)
        float4 av = *(const float4*)&A[(size_t)(m0 + aRow) * DM + k0 + aHalf * 4];
        As[(aHalf*4 + 0) * 128 + aRow] = av.x;
        As[(aHalf*4 + 1) * 128 + aRow] = av.y;
        As[(aHalf*4 + 2) * 128 + aRow] = av.z;
        As[(aHalf*4 + 3) * 128 + aRow] = av.w;
        // W tile 8x128 -> Bs[k][n]
        *(float4*)&Bs[bRow * 128 + bCol] =
            *(const float4*)&W[(size_t)(k0 + bRow) * DM + n0 + bCol];
        __syncthreads();

        #pragma unroll
        for (int kk = 0; kk < 8; kk++) {
            float a[8], b[8];
            *(float4*)&a[0] = *(float4*)&As[kk*128 + ty*8];
            *(float4*)&a[4] = *(float4*)&As[kk*128 + ty*8 + 4];
            *(float4*)&b[0] = *(float4*)&Bs[kk*128 + tx*8];
            *(float4*)&b[4] = *(float4*)&Bs[kk*128 + tx*8 + 4];
            #pragma unroll
            for (int i = 0; i < 8; i++)
                #pragma unroll
                for (int j = 0; j < 8; j++)
                    acc[i][j] += a[i] * b[j];
        }
    }
}

// ---------------------------------------------------------------
// K1: QKV projection. grid = (8, 128, 3); z picks {Q,K,V}.
// Epilogue: +bias, phi=elu+1 for Q/K, store head-major [B,H,N,Dk].
// ---------------------------------------------------------------
__global__ __launch_bounds__(256) void qkv_kernel(
    const float* __restrict__ x,
    const float* __restrict__ Wq, const float* __restrict__ bq,
    const float* __restrict__ Wk, const float* __restrict__ bk,
    const float* __restrict__ Wv, const float* __restrict__ bv)
{
    __shared__ float As[8*128];
    __shared__ float Bs[8*128];
    const int z = blockIdx.z;
    const float* W  = (z == 0) ? Wq : (z == 1) ? Wk : Wv;
    const float* bb = (z == 0) ? bq : (z == 1) ? bk : bv;
    float* dst      = (z == 0) ? g_qf : (z == 1) ? g_kf : g_v;

    const int m0 = blockIdx.y * 128;
    const int n0 = blockIdx.x * 128;

    float acc[8][8];
    #pragma unroll
    for (int i = 0; i < 8; i++)
        #pragma unroll
        for (int j = 0; j < 8; j++) acc[i][j] = 0.f;

    sgemm_tile(x, W, m0, n0, acc, As, Bs);

    const int ty = threadIdx.x >> 4, tx = threadIdx.x & 15;
    #pragma unroll
    for (int i = 0; i < 8; i++) {
        const int m = m0 + ty * 8 + i;
        const int b = m >> 9;          // /512
        const int n = m & 511;
        #pragma unroll
        for (int j = 0; j < 8; j++) {
            const int c = n0 + tx * 8 + j;
            float y = acc[i][j] + bb[c];
            if (z < 2) y = (y > 0.f) ? (y + 1.f) : __expf(y);   // elu(y)+1
            const int h = c >> 6, d = c & 63;
            dst[((((size_t)(b * NH + h)) * SEQ + n) << 6) + d] = y;
        }
    }
}

// ---------------------------------------------------------------
// K2: per (b,h): kv[d][e] = sum_n kf[n][d]*v[n][e];  ksum[d] = sum_n kf[n][d]
// grid = 512, block = 256 (16x16 threads, 4x4 micro-tile each)
// ---------------------------------------------------------------
__global__ __launch_bounds__(256) void kv_kernel()
{
    const int bh = blockIdx.x;
    const float* kf = g_kf + (size_t)bh * SEQ * DK;
    const float* v  = g_v  + (size_t)bh * SEQ * DK;

    __shared__ float kfs[32*64];
    __shared__ float vs [32*64];

    const int tid = threadIdx.x;
    const int ty = tid >> 4, tx = tid & 15;
    const int d0 = ty * 4, e0 = tx * 4;

    float acc[4][4] = {{0}};
    float ks = 0.f;

    for (int c = 0; c < SEQ; c += 32) {
        __syncthreads();
        const int base = tid * 8;
        *(float4*)&kfs[base]     = *(const float4*)&kf[(size_t)c * 64 + base];
        *(float4*)&kfs[base + 4] = *(const float4*)&kf[(size_t)c * 64 + base + 4];
        *(float4*)&vs [base]     = *(const float4*)&v [(size_t)c * 64 + base];
        *(float4*)&vs [base + 4] = *(const float4*)&v [(size_t)c * 64 + base + 4];
        __syncthreads();

        #pragma unroll 4
        for (int n = 0; n < 32; n++) {
            float a[4], b[4];
            #pragma unroll
            for (int i = 0; i < 4; i++) a[i] = kfs[n*64 + d0 + i];
            #pragma unroll
            for (int j = 0; j < 4; j++) b[j] = vs[n*64 + e0 + j];
            #pragma unroll
            for (int i = 0; i < 4; i++)
                #pragma unroll
                for (int j = 0; j < 4; j++) acc[i][j] += a[i] * b[j];
        }
        if (tid < 64) {
            #pragma unroll 8
            for (int n = 0; n < 32; n++) ks += kfs[n*64 + tid];
        }
    }

    float* kvout = g_kv + (size_t)bh * DK * DK;
    #pragma unroll
    for (int i = 0; i < 4; i++)
        #pragma unroll
        for (int j = 0; j < 4; j++)
            kvout[(d0 + i) * DK + e0 + j] = acc[i][j];
    if (tid < 64) g_ks[(size_t)bh * DK + tid] = ks;
}

// ---------------------------------------------------------------
// K3: per (b,h): out[n][e] = (qf[n]·kv[:,e]) / (qf[n]·ksum + eps)
// grid = 512, block = 256 (8 warps; warp handles rows n, lane -> e, e+32)
// writes token-major [B,N,H,Dk] so K4 is a plain GEMM
// ---------------------------------------------------------------
__global__ __launch_bounds__(256) void attn_kernel()
{
    const int bh = blockIdx.x;
    const int b = bh >> 4, h = bh & 15;

    __shared__ float kvs[64*64];
    __shared__ float kss[64];

    const int tid = threadIdx.x;
    const float* kvg = g_kv + (size_t)bh * DK * DK;
    for (int i = tid; i < 64*64; i += 256) kvs[i] = kvg[i];
    if (tid < 64) kss[tid] = g_ks[(size_t)bh * DK + tid];
    __syncthreads();

    const int warp = tid >> 5, lane = tid & 31;
    const float* qf = g_qf + (size_t)bh * SEQ * DK;

    for (int n = warp; n < SEQ; n += 8) {
        const float* qr = qf + (size_t)n * 64;
        float a0 = 0.f, a1 = 0.f, den = 0.f;
        #pragma unroll
        for (int d = 0; d < 64; d++) {
            const float q = qr[d];                 // warp-broadcast load
            a0  += q * kvs[d*64 + lane];
            a1  += q * kvs[d*64 + lane + 32];
            den += q * kss[d];
        }
        const float inv = 1.f / (den + EPSV);
        const size_t o = (((size_t)(b * SEQ + n)) * NH + h) * 64;
        g_at[o + lane]      = a0 * inv;
        g_at[o + lane + 32] = a1 * inv;
    }
}

// ---------------------------------------------------------------
// K4: final projection: d_out = g_at @ W_o + b_o   (grid = (8,128))
// ---------------------------------------------------------------
__global__ __launch_bounds__(256) void out_kernel(
    const float* __restrict__ Wo, const float* __restrict__ bo,
    float* __restrict__ out)
{
    __shared__ float As[8*128];
    __shared__ float Bs[8*128];
    const int m0 = blockIdx.y * 128;
    const int n0 = blockIdx.x * 128;

    float acc[8][8];
    #pragma unroll
    for (int i = 0; i < 8; i++)
        #pragma unroll
        for (int j = 0; j < 8; j++) acc[i][j] = 0.f;

    sgemm_tile(g_at, Wo, m0, n0, acc, As, Bs);

    const int ty = threadIdx.x >> 4, tx = threadIdx.x & 15;
    #pragma unroll
    for (int i = 0; i < 8; i++) {
        const int m = m0 + ty * 8 + i;
        #pragma unroll
        for (int j = 0; j < 8; j++) {
            const int c = n0 + tx * 8 + j;
            out[(size_t)m * DM + c] = acc[i][j] + bo[c];
        }
    }
}

// ---------------------------------------------------------------
extern "C" void kernel_launch(void* const* d_in, const int* in_sizes, int n_in,
                              void* d_out, int out_size)
{
    const float* x  = (const float*)d_in[0];
    const float* Wq = (const float*)d_in[1];
    const float* bq = (const float*)d_in[2];
    const float* Wk = (const float*)d_in[3];
    const float* bk = (const float*)d_in[4];
    const float* Wv = (const float*)d_in[5];
    const float* bv = (const float*)d_in[6];
    const float* Wo = (const float*)d_in[7];
    const float* bo = (const float*)d_in[8];
    float* out = (float*)d_out;

    dim3 gq(DM / 128, MTOK / 128, 3);      // (8, 128, 3)
    qkv_kernel<<<gq, 256>>>(x, Wq, bq, Wk, bk, Wv, bv);
    kv_kernel<<<BATCH * NH, 256>>>();      // 512 blocks
    attn_kernel<<<BATCH * NH, 256>>>();    // 512 blocks
    dim3 go(DM / 128, MTOK / 128);         // (8, 128)
    out_kernel<<<go, 256>>>(Wo, bo, out);
}

// round 5
// speedup vs baseline: 2.9385x; 2.9385x over previous
#include <cuda_runtime.h>
#include <stdint.h>

#define DM    1024
#define NH    16
#define DK    64
#define BATCH 32
#define SEQ   512
#define MTOK  (BATCH*SEQ)   // 16384
#define EPSV  1e-6f

#define BM 128
#define BN 128
#define BK 32
#define NCHUNK (DM/BK)            // 32
#define LDSROW (BK+4)             // 36 floats, pad kills bank conflicts
#define STAGE_FLOATS ((BM+BN)*LDSROW)   // 9216
#define SMEM_BYTES (2*STAGE_FLOATS*4)   // 73728

// -------- scratch (static __device__, no runtime allocation) --------
__device__ float g_xr[(size_t)MTOK * DM];        // rna(x)
__device__ float g_wt[4][(size_t)DM * DM];       // transposed+rna W{q,k,v,o}: [N,K]
__device__ float g_qf[(size_t)MTOK * DM];        // phi(Q), head-major [B,H,N,Dk]
__device__ float g_kf[(size_t)MTOK * DM];
__device__ float g_v [(size_t)MTOK * DM];
__device__ float g_at[(size_t)MTOK * DM];        // attn out (rna'd), token-major [B,N,H,Dk]
__device__ float g_kv[(size_t)BATCH * NH * DK * DK];
__device__ float g_ks[(size_t)BATCH * NH * DK];

// ------------------------ helpers ------------------------
__device__ __forceinline__ float rna_tf32(float x) {
    uint32_t u; asm("cvt.rna.tf32.f32 %0, %1;" : "=r"(u) : "f"(x));
    return __uint_as_float(u);
}
__device__ __forceinline__ uint32_t s2u(const void* p) {
    return (uint32_t)__cvta_generic_to_shared(p);
}
__device__ __forceinline__ void mma_tf32(float* c, const float* a, const float* b) {
    asm volatile(
        "mma.sync.aligned.m16n8k8.row.col.f32.tf32.tf32.f32 "
        "{%0,%1,%2,%3},{%4,%5,%6,%7},{%8,%9},{%0,%1,%2,%3};"
        : "+f"(c[0]), "+f"(c[1]), "+f"(c[2]), "+f"(c[3])
        : "r"(__float_as_uint(a[0])), "r"(__float_as_uint(a[1])),
          "r"(__float_as_uint(a[2])), "r"(__float_as_uint(a[3])),
          "r"(__float_as_uint(b[0])), "r"(__float_as_uint(b[1])));
}

// ------------------------ fused tf32 GEMM body ------------------------
// mode 0: bias+phi, head-major store (Q/K)
// mode 1: bias, head-major store (V)
// mode 2: bias, row-major store (output projection)
__device__ __forceinline__ void gemm_body(
    const float* __restrict__ A, const float* __restrict__ Bt,
    const float* __restrict__ bias, float* __restrict__ dst,
    int m0, int n0, int mode)
{
    extern __shared__ float smf[];
    const int tid  = threadIdx.x;
    const int wid  = tid >> 5, lane = tid & 31;
    const int wm   = wid >> 2, wn   = wid & 3;   // 2 x 4 warp grid
    const int g    = lane >> 2, tig = lane & 3;

    float acc[4][4][4];
    #pragma unroll
    for (int mt = 0; mt < 4; mt++)
        #pragma unroll
        for (int nt = 0; nt < 4; nt++)
            #pragma unroll
            for (int q = 0; q < 4; q++) acc[mt][nt][q] = 0.f;

    // issue async load of one K-chunk into stage s
    auto issue_load = [&](int s, int k0) {
        float* base = smf + s * STAGE_FLOATS;
        uint32_t sA = s2u(base);
        uint32_t sB = s2u(base + BM * LDSROW);
        #pragma unroll
        for (int i = 0; i < 4; i++) {
            int idx = tid + i * 256;          // 0..1023
            int row = idx >> 3, seg = idx & 7;
            const float* srcA = A  + (size_t)(m0 + row) * DM + k0 + seg * 4;
            const float* srcB = Bt + (size_t)(n0 + row) * DM + k0 + seg * 4;
            uint32_t off = (uint32_t)(row * LDSROW + seg * 4) * 4;
            asm volatile("cp.async.cg.shared.global [%0], [%1], 16;" :: "r"(sA + off), "l"(srcA));
            asm volatile("cp.async.cg.shared.global [%0], [%1], 16;" :: "r"(sB + off), "l"(srcB));
        }
        asm volatile("cp.async.commit_group;");
    };

    issue_load(0, 0);
    for (int kc = 0; kc < NCHUNK; kc++) {
        const int cur = kc & 1;
        if (kc + 1 < NCHUNK) {
            issue_load(cur ^ 1, (kc + 1) * BK);
            asm volatile("cp.async.wait_group 1;");
        } else {
            asm volatile("cp.async.wait_group 0;");
        }
        __syncthreads();

        const float* as = smf + cur * STAGE_FLOATS + (wm * 64) * LDSROW;
        const float* bs = smf + cur * STAGE_FLOATS + BM * LDSROW + (wn * 32) * LDSROW;

        #pragma unroll
        for (int kk = 0; kk < 4; kk++) {
            const int c0 = kk * 8 + tig;
            float a[4][4], b[4][2];
            #pragma unroll
            for (int mt = 0; mt < 4; mt++) {
                const float* p = as + (mt * 16 + g) * LDSROW + c0;
                a[mt][0] = p[0];
                a[mt][1] = p[8 * LDSROW];
                a[mt][2] = p[4];
                a[mt][3] = p[8 * LDSROW + 4];
            }
            #pragma unroll
            for (int nt = 0; nt < 4; nt++) {
                const float* p = bs + (nt * 8 + g) * LDSROW + c0;
                b[nt][0] = p[0];
                b[nt][1] = p[4];
            }
            #pragma unroll
            for (int mt = 0; mt < 4; mt++)
                #pragma unroll
                for (int nt = 0; nt < 4; nt++)
                    mma_tf32(acc[mt][nt], a[mt], b[nt]);
        }
        __syncthreads();
    }

    // epilogue: per-fragment direct stores (float2)
    const int mbase = m0 + wm * 64;
    const int nb    = n0 + wn * 32;
    #pragma unroll
    for (int mt = 0; mt < 4; mt++) {
        #pragma unroll
        for (int half = 0; half < 2; half++) {
            const int m = mbase + mt * 16 + g + half * 8;
            #pragma unroll
            for (int nt = 0; nt < 4; nt++) {
                const int c = nb + nt * 8 + 2 * tig;
                float v0 = acc[mt][nt][half * 2 + 0] + bias[c];
                float v1 = acc[mt][nt][half * 2 + 1] + bias[c + 1];
                if (mode == 0) {
                    v0 = (v0 > 0.f) ? (v0 + 1.f) : __expf(v0);
                    v1 = (v1 > 0.f) ? (v1 + 1.f) : __expf(v1);
                }
                float2 v = make_float2(v0, v1);
                if (mode == 2) {
                    *(float2*)&dst[(size_t)m * DM + c] = v;
                } else {
                    const int b = m >> 9, n = m & 511;
                    const int h = c >> 6, d = c & 63;
                    *(float2*)&dst[((((size_t)(b * NH + h)) * SEQ + n) << 6) + d] = v;
                }
            }
        }
    }
}

// ------------------------ kernels ------------------------
__global__ __launch_bounds__(256) void qkv_mma(
    const float* __restrict__ bq, const float* __restrict__ bk, const float* __restrict__ bv)
{
    const int z = blockIdx.z;
    const float* bias = (z == 0) ? bq : (z == 1) ? bk : bv;
    float* dst        = (z == 0) ? g_qf : (z == 1) ? g_kf : g_v;
    gemm_body(g_xr, g_wt[z], bias, dst,
              blockIdx.y * BM, blockIdx.x * BN, (z < 2) ? 0 : 1);
}

__global__ __launch_bounds__(256) void out_mma(
    const float* __restrict__ bo, float* __restrict__ out)
{
    gemm_body(g_at, g_wt[3], bo, out, blockIdx.y * BM, blockIdx.x * BN, 2);
}

// rna-round x into g_xr (float4)
__global__ __launch_bounds__(256) void rna_x_kernel(const float* __restrict__ x)
{
    int idx = blockIdx.x * 256 + threadIdx.x;
    float4 v = ((const float4*)x)[idx];
    v.x = rna_tf32(v.x); v.y = rna_tf32(v.y); v.z = rna_tf32(v.z); v.w = rna_tf32(v.w);
    ((float4*)g_xr)[idx] = v;
}

// transpose + rna W[k][n] -> Wt[n][k] for the 4 weight matrices
__global__ __launch_bounds__(256) void transpose_w(
    const float* __restrict__ Wq, const float* __restrict__ Wk,
    const float* __restrict__ Wv, const float* __restrict__ Wo)
{
    const int z = blockIdx.z;
    const float* W = (z == 0) ? Wq : (z == 1) ? Wk : (z == 2) ? Wv : Wo;
    float* dst = g_wt[z];
    __shared__ float t[32][33];
    const int k0 = blockIdx.x * 32, n0 = blockIdx.y * 32;
    const int tx = threadIdx.x & 31, ty = threadIdx.x >> 5;  // 32x8
    #pragma unroll
    for (int i = 0; i < 4; i++)
        t[ty + i*8][tx] = rna_tf32(W[(size_t)(k0 + ty + i*8) * DM + n0 + tx]);
    __syncthreads();
    #pragma unroll
    for (int i = 0; i < 4; i++)
        dst[(size_t)(n0 + ty + i*8) * DM + k0 + tx] = t[tx][ty + i*8];
}

// K2: per (b,h): kv[d][e] = sum_n kf[n][d]*v[n][e]; ksum[d] = sum_n kf[n][d]
__global__ __launch_bounds__(256) void kv_kernel()
{
    const int bh = blockIdx.x;
    const float* kf = g_kf + (size_t)bh * SEQ * DK;
    const float* v  = g_v  + (size_t)bh * SEQ * DK;

    __shared__ float kfs[32*64];
    __shared__ float vs [32*64];

    const int tid = threadIdx.x;
    const int ty = tid >> 4, tx = tid & 15;
    const int d0 = ty * 4, e0 = tx * 4;

    float acc[4][4] = {{0}};
    float ks = 0.f;

    for (int c = 0; c < SEQ; c += 32) {
        __syncthreads();
        const int base = tid * 8;
        *(float4*)&kfs[base]     = *(const float4*)&kf[(size_t)c * 64 + base];
        *(float4*)&kfs[base + 4] = *(const float4*)&kf[(size_t)c * 64 + base + 4];
        *(float4*)&vs [base]     = *(const float4*)&v [(size_t)c * 64 + base];
        *(float4*)&vs [base + 4] = *(const float4*)&v [(size_t)c * 64 + base + 4];
        __syncthreads();

        #pragma unroll 4
        for (int n = 0; n < 32; n++) {
            float a[4], b[4];
            #pragma unroll
            for (int i = 0; i < 4; i++) a[i] = kfs[n*64 + d0 + i];
            #pragma unroll
            for (int j = 0; j < 4; j++) b[j] = vs[n*64 + e0 + j];
            #pragma unroll
            for (int i = 0; i < 4; i++)
                #pragma unroll
                for (int j = 0; j < 4; j++) acc[i][j] += a[i] * b[j];
        }
        if (tid < 64) {
            #pragma unroll 8
            for (int n = 0; n < 32; n++) ks += kfs[n*64 + tid];
        }
    }

    float* kvout = g_kv + (size_t)bh * DK * DK;
    #pragma unroll
    for (int i = 0; i < 4; i++)
        #pragma unroll
        for (int j = 0; j < 4; j++)
            kvout[(d0 + i) * DK + e0 + j] = acc[i][j];
    if (tid < 64) g_ks[(size_t)bh * DK + tid] = ks;
}

// K3: readout; stores rna-rounded token-major [B,N,H,Dk] (feeds tf32 out GEMM)
__global__ __launch_bounds__(256) void attn_kernel()
{
    const int bh = blockIdx.x;
    const int b = bh >> 4, h = bh & 15;

    __shared__ float kvs[64*64];
    __shared__ float kss[64];

    const int tid = threadIdx.x;
    const float* kvg = g_kv + (size_t)bh * DK * DK;
    for (int i = tid; i < 64*64; i += 256) kvs[i] = kvg[i];
    if (tid < 64) kss[tid] = g_ks[(size_t)bh * DK + tid];
    __syncthreads();

    const int warp = tid >> 5, lane = tid & 31;
    const float* qf = g_qf + (size_t)bh * SEQ * DK;

    for (int n = warp; n < SEQ; n += 8) {
        const float* qr = qf + (size_t)n * 64;
        float a0 = 0.f, a1 = 0.f, den = 0.f;
        #pragma unroll
        for (int d = 0; d < 64; d++) {
            const float q = qr[d];
            a0  += q * kvs[d*64 + lane];
            a1  += q * kvs[d*64 + lane + 32];
            den += q * kss[d];
        }
        const float inv = 1.f / (den + EPSV);
        const size_t o = (((size_t)(b * SEQ + n)) * NH + h) * 64;
        g_at[o + lane]      = rna_tf32(a0 * inv);
        g_at[o + lane + 32] = rna_tf32(a1 * inv);
    }
}

// ---------------------------------------------------------------
extern "C" void kernel_launch(void* const* d_in, const int* in_sizes, int n_in,
                              void* d_out, int out_size)
{
    const float* x  = (const float*)d_in[0];
    const float* Wq = (const float*)d_in[1];
    const float* bq = (const float*)d_in[2];
    const float* Wk = (const float*)d_in[3];
    const float* bk = (const float*)d_in[4];
    const float* Wv = (const float*)d_in[5];
    const float* bv = (const float*)d_in[6];
    const float* Wo = (const float*)d_in[7];
    const float* bo = (const float*)d_in[8];
    float* out = (float*)d_out;

    static bool attr_done = false;
    if (!attr_done) {
        cudaFuncSetAttribute(qkv_mma, cudaFuncAttributeMaxDynamicSharedMemorySize, SMEM_BYTES);
        cudaFuncSetAttribute(out_mma, cudaFuncAttributeMaxDynamicSharedMemorySize, SMEM_BYTES);
        attr_done = true;
    }

    rna_x_kernel<<<(MTOK * DM / 4) / 256, 256>>>(x);
    transpose_w<<<dim3(DM/32, DM/32, 4), 256>>>(Wq, Wk, Wv, Wo);

    dim3 gq(DM / BN, MTOK / BM, 3);          // (8, 128, 3)
    qkv_mma<<<gq, 256, SMEM_BYTES>>>(bq, bk, bv);

    kv_kernel<<<BATCH * NH, 256>>>();
    attn_kernel<<<BATCH * NH, 256>>>();

    dim3 go(DM / BN, MTOK / BM);             // (8, 128)
    out_mma<<<go, 256, SMEM_BYTES>>>(bo, out);
}

// round 6
// speedup vs baseline: 4.1193x; 1.4019x over previous
#include <cuda_runtime.h>
#include <cuda_fp16.h>
#include <stdint.h>

#define DM    1024
#define NH    16
#define DK    64
#define BATCH 32
#define SEQ   512
#define MTOK  (BATCH*SEQ)   // 16384
#define EPSV  1e-6f

#define BM 128
#define BN 128
#define BK 32                      // halves per K chunk
#define NCHUNK (DM/BK)             // 32
#define LDSROW 20                  // row stride in b32 units (32 halves + 8 pad)
#define STAGE_U32 ((BM+BN)*LDSROW) // 5120 u32 = 20KB
#define SMEM_BYTES (2*STAGE_U32*4) // 40960

// -------- scratch (static __device__, no runtime allocation) --------
__device__ __half g_xh[(size_t)MTOK * DM];       // half(x)
__device__ __half g_wth[4][(size_t)DM * DM];     // transposed half W{q,k,v,o}: [N,K]
__device__ float  g_qf[(size_t)MTOK * DM];       // phi(Q), head-major [B,H,N,Dk]
__device__ float  g_kf[(size_t)MTOK * DM];
__device__ float  g_v [(size_t)MTOK * DM];
__device__ __half g_ath[(size_t)MTOK * DM];      // attn out (half), token-major [B,N,H,Dk]
__device__ float  g_kv[(size_t)BATCH * NH * DK * DK];
__device__ float  g_ks[(size_t)BATCH * NH * DK];

// ------------------------ helpers ------------------------
__device__ __forceinline__ uint32_t s2u(const void* p) {
    return (uint32_t)__cvta_generic_to_shared(p);
}
__device__ __forceinline__ void mma_f16(float* c, const uint32_t* a, const uint32_t* b) {
    asm volatile(
        "mma.sync.aligned.m16n8k16.row.col.f32.f16.f16.f32 "
        "{%0,%1,%2,%3},{%4,%5,%6,%7},{%8,%9},{%0,%1,%2,%3};"
        : "+f"(c[0]), "+f"(c[1]), "+f"(c[2]), "+f"(c[3])
        : "r"(a[0]), "r"(a[1]), "r"(a[2]), "r"(a[3]),
          "r"(b[0]), "r"(b[1]));
}

// ------------------------ fused fp16 GEMM body ------------------------
// A: [M,1024] half row-major; Bt: [N,1024] half row-major (W^T)
// mode 0: bias+phi, head-major store (Q/K)
// mode 1: bias, head-major store (V)
// mode 2: bias, row-major store (output projection)
__device__ __forceinline__ void gemm_body(
    const __half* __restrict__ A, const __half* __restrict__ Bt,
    const float* __restrict__ bias, float* __restrict__ dstf,
    __half* __restrict__ dsth, int m0, int n0, int mode)
{
    extern __shared__ uint32_t smu[];
    const int tid  = threadIdx.x;
    const int wid  = tid >> 5, lane = tid & 31;
    const int wm   = wid >> 2, wn   = wid & 3;   // 2 x 4 warp grid
    const int g    = lane >> 2, tig = lane & 3;

    float acc[4][4][4];
    #pragma unroll
    for (int mt = 0; mt < 4; mt++)
        #pragma unroll
        for (int nt = 0; nt < 4; nt++)
            #pragma unroll
            for (int q = 0; q < 4; q++) acc[mt][nt][q] = 0.f;

    // async load of one K-chunk (BK=32 halves/row) into stage s
    auto issue_load = [&](int s, int k0) {
        uint32_t sA = s2u(smu + s * STAGE_U32);
        uint32_t sB = sA + BM * LDSROW * 4;
        #pragma unroll
        for (int i = 0; i < 2; i++) {
            int idx = tid + i * 256;          // 0..511
            int row = idx >> 2, seg = idx & 3;  // 4 x 16B segments per 64B row
            const __half* srcA = A  + (size_t)(m0 + row) * DM + k0 + seg * 8;
            const __half* srcB = Bt + (size_t)(n0 + row) * DM + k0 + seg * 8;
            uint32_t off = (uint32_t)(row * LDSROW * 4 + seg * 16);
            asm volatile("cp.async.cg.shared.global [%0], [%1], 16;" :: "r"(sA + off), "l"(srcA));
            asm volatile("cp.async.cg.shared.global [%0], [%1], 16;" :: "r"(sB + off), "l"(srcB));
        }
        asm volatile("cp.async.commit_group;");
    };

    issue_load(0, 0);
    for (int kc = 0; kc < NCHUNK; kc++) {
        const int cur = kc & 1;
        if (kc + 1 < NCHUNK) {
            issue_load(cur ^ 1, (kc + 1) * BK);
            asm volatile("cp.async.wait_group 1;");
        } else {
            asm volatile("cp.async.wait_group 0;");
        }
        __syncthreads();

        const uint32_t* as = smu + cur * STAGE_U32 + (wm * 64) * LDSROW;
        const uint32_t* bs = smu + cur * STAGE_U32 + BM * LDSROW + (wn * 32) * LDSROW;

        #pragma unroll
        for (int kk = 0; kk < 2; kk++) {          // two k16 blocks per BK=32
            const int c0 = kk * 8 + tig;          // b32 column
            uint32_t a[4][4], b[4][2];
            #pragma unroll
            for (int mt = 0; mt < 4; mt++) {
                const uint32_t* p = as + (mt * 16 + g) * LDSROW + c0;
                a[mt][0] = p[0];                  // (row g,   k=2c0..2c0+1)
                a[mt][1] = p[8 * LDSROW];         // (row g+8, k=2c0..)
                a[mt][2] = p[4];                  // (row g,   k=2c0+8..)
                a[mt][3] = p[8 * LDSROW + 4];     // (row g+8, k=2c0+8..)
            }
            #pragma unroll
            for (int nt = 0; nt < 4; nt++) {
                const uint32_t* p = bs + (nt * 8 + g) * LDSROW + c0;
                b[nt][0] = p[0];                  // (n=g, k=2c0..2c0+1)
                b[nt][1] = p[4];                  // (n=g, k=2c0+8..)
            }
            #pragma unroll
            for (int mt = 0; mt < 4; mt++)
                #pragma unroll
                for (int nt = 0; nt < 4; nt++)
                    mma_f16(acc[mt][nt], a[mt], b[nt]);
        }
        __syncthreads();
    }

    // epilogue: per-fragment direct stores
    const int mbase = m0 + wm * 64;
    const int nb    = n0 + wn * 32;
    #pragma unroll
    for (int mt = 0; mt < 4; mt++) {
        #pragma unroll
        for (int half = 0; half < 2; half++) {
            const int m = mbase + mt * 16 + g + half * 8;
            #pragma unroll
            for (int nt = 0; nt < 4; nt++) {
                const int c = nb + nt * 8 + 2 * tig;
                float v0 = acc[mt][nt][half * 2 + 0] + bias[c];
                float v1 = acc[mt][nt][half * 2 + 1] + bias[c + 1];
                if (mode == 0) {
                    v0 = (v0 > 0.f) ? (v0 + 1.f) : __expf(v0);
                    v1 = (v1 > 0.f) ? (v1 + 1.f) : __expf(v1);
                }
                if (mode == 2) {
                    *(float2*)&dstf[(size_t)m * DM + c] = make_float2(v0, v1);
                } else {
                    const int b = m >> 9, n = m & 511;
                    const int h = c >> 6, d = c & 63;
                    *(float2*)&dstf[((((size_t)(b * NH + h)) * SEQ + n) << 6) + d] =
                        make_float2(v0, v1);
                }
            }
        }
    }
    (void)dsth;
}

// ------------------------ kernels ------------------------
__global__ __launch_bounds__(256) void qkv_mma(
    const float* __restrict__ bq, const float* __restrict__ bk, const float* __restrict__ bv)
{
    const int z = blockIdx.z;
    const float* bias = (z == 0) ? bq : (z == 1) ? bk : bv;
    float* dst        = (z == 0) ? g_qf : (z == 1) ? g_kf : g_v;
    gemm_body(g_xh, g_wth[z], bias, dst, nullptr,
              blockIdx.y * BM, blockIdx.x * BN, (z < 2) ? 0 : 1);
}

__global__ __launch_bounds__(256) void out_mma(
    const float* __restrict__ bo, float* __restrict__ out)
{
    gemm_body(g_ath, g_wth[3], bo, out, nullptr, blockIdx.y * BM, blockIdx.x * BN, 2);
}

// convert x -> half
__global__ __launch_bounds__(256) void cvt_x_kernel(const float* __restrict__ x)
{
    int idx = blockIdx.x * 256 + threadIdx.x;       // float4 index
    float4 v = ((const float4*)x)[idx];
    __half2 h0 = __floats2half2_rn(v.x, v.y);
    __half2 h1 = __floats2half2_rn(v.z, v.w);
    ((__half2*)g_xh)[idx * 2 + 0] = h0;
    ((__half2*)g_xh)[idx * 2 + 1] = h1;
}

// transpose + half W[k][n] -> Wt[n][k] for the 4 weight matrices
__global__ __launch_bounds__(256) void transpose_w(
    const float* __restrict__ Wq, const float* __restrict__ Wk,
    const float* __restrict__ Wv, const float* __restrict__ Wo)
{
    const int z = blockIdx.z;
    const float* W = (z == 0) ? Wq : (z == 1) ? Wk : (z == 2) ? Wv : Wo;
    __half* dst = g_wth[z];
    __shared__ float t[32][33];
    const int k0 = blockIdx.x * 32, n0 = blockIdx.y * 32;
    const int tx = threadIdx.x & 31, ty = threadIdx.x >> 5;  // 32x8
    #pragma unroll
    for (int i = 0; i < 4; i++)
        t[ty + i*8][tx] = W[(size_t)(k0 + ty + i*8) * DM + n0 + tx];
    __syncthreads();
    #pragma unroll
    for (int i = 0; i < 4; i++)
        dst[(size_t)(n0 + ty + i*8) * DM + k0 + tx] = __float2half_rn(t[tx][ty + i*8]);
}

// K2: per (b,h): kv[d][e] = sum_n kf[n][d]*v[n][e]; ksum[d] = sum_n kf[n][d]
__global__ __launch_bounds__(256) void kv_kernel()
{
    const int bh = blockIdx.x;
    const float* kf = g_kf + (size_t)bh * SEQ * DK;
    const float* v  = g_v  + (size_t)bh * SEQ * DK;

    __shared__ float kfs[32*64];
    __shared__ float vs [32*64];

    const int tid = threadIdx.x;
    const int ty = tid >> 4, tx = tid & 15;
    const int d0 = ty * 4, e0 = tx * 4;

    float acc[4][4] = {{0}};
    float ks = 0.f;

    for (int c = 0; c < SEQ; c += 32) {
        __syncthreads();
        const int base = tid * 8;
        *(float4*)&kfs[base]     = *(const float4*)&kf[(size_t)c * 64 + base];
        *(float4*)&kfs[base + 4] = *(const float4*)&kf[(size_t)c * 64 + base + 4];
        *(float4*)&vs [base]     = *(const float4*)&v [(size_t)c * 64 + base];
        *(float4*)&vs [base + 4] = *(const float4*)&v [(size_t)c * 64 + base + 4];
        __syncthreads();

        #pragma unroll 4
        for (int n = 0; n < 32; n++) {
            float a[4], b[4];
            #pragma unroll
            for (int i = 0; i < 4; i++) a[i] = kfs[n*64 + d0 + i];
            #pragma unroll
            for (int j = 0; j < 4; j++) b[j] = vs[n*64 + e0 + j];
            #pragma unroll
            for (int i = 0; i < 4; i++)
                #pragma unroll
                for (int j = 0; j < 4; j++) acc[i][j] += a[i] * b[j];
        }
        if (tid < 64) {
            #pragma unroll 8
            for (int n = 0; n < 32; n++) ks += kfs[n*64 + tid];
        }
    }

    float* kvout = g_kv + (size_t)bh * DK * DK;
    #pragma unroll
    for (int i = 0; i < 4; i++)
        #pragma unroll
        for (int j = 0; j < 4; j++)
            kvout[(d0 + i) * DK + e0 + j] = acc[i][j];
    if (tid < 64) g_ks[(size_t)bh * DK + tid] = ks;
}

// K3: readout; stores half token-major [B,N,H,Dk] (feeds fp16 out GEMM)
__global__ __launch_bounds__(256) void attn_kernel()
{
    const int bh = blockIdx.x;
    const int b = bh >> 4, h = bh & 15;

    __shared__ float kvs[64*64];
    __shared__ float kss[64];

    const int tid = threadIdx.x;
    const float* kvg = g_kv + (size_t)bh * DK * DK;
    for (int i = tid; i < 64*64; i += 256) kvs[i] = kvg[i];
    if (tid < 64) kss[tid] = g_ks[(size_t)bh * DK + tid];
    __syncthreads();

    const int warp = tid >> 5, lane = tid & 31;
    const float* qf = g_qf + (size_t)bh * SEQ * DK;

    for (int n = warp; n < SEQ; n += 8) {
        const float* qr = qf + (size_t)n * 64;
        float a0 = 0.f, a1 = 0.f, den = 0.f;
        #pragma unroll
        for (int d = 0; d < 64; d++) {
            const float q = qr[d];
            a0  += q * kvs[d*64 + lane];
            a1  += q * kvs[d*64 + lane + 32];
            den += q * kss[d];
        }
        const float inv = 1.f / (den + EPSV);
        const size_t o = (((size_t)(b * SEQ + n)) * NH + h) * 64;
        g_ath[o + lane]      = __float2half_rn(a0 * inv);
        g_ath[o + lane + 32] = __float2half_rn(a1 * inv);
    }
}

// ---------------------------------------------------------------
extern "C" void kernel_launch(void* const* d_in, const int* in_sizes, int n_in,
                              void* d_out, int out_size)
{
    const float* x  = (const float*)d_in[0];
    const float* Wq = (const float*)d_in[1];
    const float* bq = (const float*)d_in[2];
    const float* Wk = (const float*)d_in[3];
    const float* bk = (const float*)d_in[4];
    const float* Wv = (const float*)d_in[5];
    const float* bv = (const float*)d_in[6];
    const float* Wo = (const float*)d_in[7];
    const float* bo = (const float*)d_in[8];
    float* out = (float*)d_out;

    static bool attr_done = false;
    if (!attr_done) {
        cudaFuncSetAttribute(qkv_mma, cudaFuncAttributeMaxDynamicSharedMemorySize, SMEM_BYTES);
        cudaFuncSetAttribute(out_mma, cudaFuncAttributeMaxDynamicSharedMemorySize, SMEM_BYTES);
        attr_done = true;
    }

    cvt_x_kernel<<<(MTOK * DM / 4) / 256, 256>>>(x);
    transpose_w<<<dim3(DM/32, DM/32, 4), 256>>>(Wq, Wk, Wv, Wo);

    dim3 gq(DM / BN, MTOK / BM, 3);          // (8, 128, 3)
    qkv_mma<<<gq, 256, SMEM_BYTES>>>(bq, bk, bv);

    kv_kernel<<<BATCH * NH, 256>>>();
    attn_kernel<<<BATCH * NH, 256>>>();

    dim3 go(DM / BN, MTOK / BM);             // (8, 128)
    out_mma<<<go, 256, SMEM_BYTES>>>(bo, out);
}

// round 7
// speedup vs baseline: 4.8010x; 1.1655x over previous
#include <cuda_runtime.h>
#include <cuda_fp16.h>
#include <stdint.h>

#define DM    1024
#define NH    16
#define DK    64
#define BATCH 32
#define SEQ   512
#define MTOK  (BATCH*SEQ)   // 16384
#define EPSV  1e-6f

#define BM 128
#define BN 128
#define BK 64                        // halves per K chunk (128B row)
#define NCH (DM/BK)                  // 16
#define ROWB 144                     // padded row stride in bytes (128 + 16)
#define STAGE_BYTES ((BM+BN)*ROWB)   // 36864
#define SMEM_BYTES (3*STAGE_BYTES)   // 110592

// -------- scratch (static __device__, no runtime allocation) --------
__device__ __half g_xh[(size_t)MTOK * DM];       // half(x)
__device__ __half g_wth[4][(size_t)DM * DM];     // transposed half W{q,k,v,o}: [N,K]
__device__ __half g_qfh[(size_t)MTOK * DM];      // phi(Q) half, head-major [B,H,N,Dk]
__device__ __half g_kfh[(size_t)MTOK * DM];      // phi(K) half, head-major
__device__ __half g_vh [(size_t)MTOK * DM];      // V half, head-major
__device__ __half g_ath[(size_t)MTOK * DM];      // attn out half, token-major [B,N,H,Dk]
__device__ float  g_kv[(size_t)BATCH * NH * DK * DK];
__device__ float  g_ks[(size_t)BATCH * NH * DK];

// ------------------------ helpers ------------------------
__device__ __forceinline__ uint32_t s2u(const void* p) {
    return (uint32_t)__cvta_generic_to_shared(p);
}
__device__ __forceinline__ void mma_f16(float* c, const uint32_t* a, const uint32_t* b) {
    asm volatile(
        "mma.sync.aligned.m16n8k16.row.col.f32.f16.f16.f32 "
        "{%0,%1,%2,%3},{%4,%5,%6,%7},{%8,%9},{%0,%1,%2,%3};"
        : "+f"(c[0]), "+f"(c[1]), "+f"(c[2]), "+f"(c[3])
        : "r"(a[0]), "r"(a[1]), "r"(a[2]), "r"(a[3]),
          "r"(b[0]), "r"(b[1]));
}
__device__ __forceinline__ void ldsm_x4(uint32_t& r0, uint32_t& r1, uint32_t& r2,
                                        uint32_t& r3, uint32_t addr) {
    asm volatile("ldmatrix.sync.aligned.m8n8.x4.shared.b16 {%0,%1,%2,%3}, [%4];"
                 : "=r"(r0), "=r"(r1), "=r"(r2), "=r"(r3) : "r"(addr));
}

// ------------------------ fused fp16 GEMM body ------------------------
// A:[M,1024] half row-major; Bt:[N,1024] half row-major (W^T)
// mode 0: bias+phi -> half head-major; 1: bias -> half head-major; 2: bias -> fp32 row-major
__device__ __forceinline__ void gemm_body(
    const __half* __restrict__ A, const __half* __restrict__ Bt,
    const float* __restrict__ bias, float* __restrict__ dstf,
    __half* __restrict__ dsth, int m0, int n0, int mode)
{
    extern __shared__ char smc[];
    const uint32_t smb = s2u(smc);
    const int tid  = threadIdx.x;
    const int wid  = tid >> 5, lane = tid & 31;
    const int wm   = wid >> 2, wn   = wid & 3;   // 2 x 4 warp grid
    const int g    = lane >> 2, tig = lane & 3;

    float acc[4][4][4];
    #pragma unroll
    for (int mt = 0; mt < 4; mt++)
        #pragma unroll
        for (int nt = 0; nt < 4; nt++)
            #pragma unroll
            for (int q = 0; q < 4; q++) acc[mt][nt][q] = 0.f;

    // per-lane ldmatrix offsets (bytes within a stage)
    const uint32_t aOff = (uint32_t)((lane & 15) * ROWB + (lane >> 4) * 16);
    const uint32_t bOff = (uint32_t)(((lane & 7) + ((lane >> 4) << 3)) * ROWB
                                     + ((lane >> 3) & 1) * 16);

    // async load of one K-chunk (BK=64 halves/row) into stage s
    auto issue_load = [&](int s, int k0) {
        const uint32_t sb = smb + (uint32_t)s * STAGE_BYTES;
        #pragma unroll
        for (int i = 0; i < 4; i++) {                 // A rows 0..127
            int idx = tid + i * 256, row = idx >> 3, seg = idx & 7;
            const __half* src = A + (size_t)(m0 + row) * DM + k0 + seg * 8;
            asm volatile("cp.async.cg.shared.global [%0], [%1], 16;"
                         :: "r"(sb + (uint32_t)(row * ROWB + seg * 16)), "l"(src));
        }
        #pragma unroll
        for (int i = 4; i < 8; i++) {                 // B rows 128..255
            int idx = tid + i * 256, row = idx >> 3, seg = idx & 7;
            const __half* src = Bt + (size_t)(n0 + row - 128) * DM + k0 + seg * 8;
            asm volatile("cp.async.cg.shared.global [%0], [%1], 16;"
                         :: "r"(sb + (uint32_t)(row * ROWB + seg * 16)), "l"(src));
        }
        asm volatile("cp.async.commit_group;");
    };

    issue_load(0, 0);
    issue_load(1, BK);

    #pragma unroll 1
    for (int kc = 0; kc < NCH; kc++) {
        if (kc < NCH - 1) asm volatile("cp.async.wait_group 1;");
        else              asm volatile("cp.async.wait_group 0;");
        __syncthreads();

        if (kc + 2 < NCH) issue_load((kc + 2) % 3, (kc + 2) * BK);

        const uint32_t sb    = smb + (uint32_t)(kc % 3) * STAGE_BYTES;
        const uint32_t aWarp = sb + (uint32_t)(wm * 64) * ROWB + aOff;
        const uint32_t bWarp = sb + (uint32_t)(128 + wn * 32) * ROWB + bOff;

        #pragma unroll
        for (int kk = 0; kk < 4; kk++) {              // 4 x k16 per BK=64
            uint32_t a[4][4], b[4][2];
            #pragma unroll
            for (int mt = 0; mt < 4; mt++)
                ldsm_x4(a[mt][0], a[mt][1], a[mt][2], a[mt][3],
                        aWarp + (uint32_t)(mt * 16 * ROWB + kk * 32));
            ldsm_x4(b[0][0], b[0][1], b[1][0], b[1][1], bWarp + (uint32_t)(kk * 32));
            ldsm_x4(b[2][0], b[2][1], b[3][0], b[3][1],
                    bWarp + (uint32_t)(16 * ROWB + kk * 32));
            #pragma unroll
            for (int mt = 0; mt < 4; mt++)
                #pragma unroll
                for (int nt = 0; nt < 4; nt++)
                    mma_f16(acc[mt][nt], a[mt], b[nt]);
        }
    }

    // epilogue
    const int mbase = m0 + wm * 64;
    const int nb    = n0 + wn * 32;
    #pragma unroll
    for (int mt = 0; mt < 4; mt++) {
        #pragma unroll
        for (int half = 0; half < 2; half++) {
            const int m = mbase + mt * 16 + g + half * 8;
            #pragma unroll
            for (int nt = 0; nt < 4; nt++) {
                const int c = nb + nt * 8 + 2 * tig;
                float v0 = acc[mt][nt][half * 2 + 0] + bias[c];
                float v1 = acc[mt][nt][half * 2 + 1] + bias[c + 1];
                if (mode == 0) {
                    v0 = (v0 > 0.f) ? (v0 + 1.f) : __expf(v0);
                    v1 = (v1 > 0.f) ? (v1 + 1.f) : __expf(v1);
                }
                if (mode == 2) {
                    *(float2*)&dstf[(size_t)m * DM + c] = make_float2(v0, v1);
                } else {
                    const int b = m >> 9, n = m & 511;
                    const int h = c >> 6, d = c & 63;
                    *(__half2*)&dsth[((((size_t)(b * NH + h)) * SEQ + n) << 6) + d] =
                        __floats2half2_rn(v0, v1);
                }
            }
        }
    }
}

// ------------------------ kernels ------------------------
__global__ __launch_bounds__(256) void qkv_mma(
    const float* __restrict__ bq, const float* __restrict__ bk, const float* __restrict__ bv)
{
    const int z = blockIdx.z;
    const float* bias = (z == 0) ? bq : (z == 1) ? bk : bv;
    __half* dst       = (z == 0) ? g_qfh : (z == 1) ? g_kfh : g_vh;
    gemm_body(g_xh, g_wth[z], bias, nullptr, dst,
              blockIdx.y * BM, blockIdx.x * BN, (z < 2) ? 0 : 1);
}

__global__ __launch_bounds__(256) void out_mma(
    const float* __restrict__ bo, float* __restrict__ out)
{
    gemm_body(g_ath, g_wth[3], bo, out, nullptr, blockIdx.y * BM, blockIdx.x * BN, 2);
}

// convert x -> half
__global__ __launch_bounds__(256) void cvt_x_kernel(const float* __restrict__ x)
{
    int idx = blockIdx.x * 256 + threadIdx.x;       // float4 index
    float4 v = ((const float4*)x)[idx];
    ((__half2*)g_xh)[idx * 2 + 0] = __floats2half2_rn(v.x, v.y);
    ((__half2*)g_xh)[idx * 2 + 1] = __floats2half2_rn(v.z, v.w);
}

// transpose + half W[k][n] -> Wt[n][k] for the 4 weight matrices
__global__ __launch_bounds__(256) void transpose_w(
    const float* __restrict__ Wq, const float* __restrict__ Wk,
    const float* __restrict__ Wv, const float* __restrict__ Wo)
{
    const int z = blockIdx.z;
    const float* W = (z == 0) ? Wq : (z == 1) ? Wk : (z == 2) ? Wv : Wo;
    __half* dst = g_wth[z];
    __shared__ float t[32][33];
    const int k0 = blockIdx.x * 32, n0 = blockIdx.y * 32;
    const int tx = threadIdx.x & 31, ty = threadIdx.x >> 5;  // 32x8
    #pragma unroll
    for (int i = 0; i < 4; i++)
        t[ty + i*8][tx] = W[(size_t)(k0 + ty + i*8) * DM + n0 + tx];
    __syncthreads();
    #pragma unroll
    for (int i = 0; i < 4; i++)
        dst[(size_t)(n0 + ty + i*8) * DM + k0 + tx] = __float2half_rn(t[tx][ty + i*8]);
}

// K2: per (b,h): kv[d][e] = sum_n kf[n][d]*v[n][e]; ksum[d] = sum_n kf[n][d]
// half inputs, cp.async double-buffered 64-row chunks, fused ksum
__global__ __launch_bounds__(256) void kv_kernel()
{
    const int bh = blockIdx.x;
    const __half* kf = g_kfh + (size_t)bh * SEQ * DK;
    const __half* v  = g_vh  + (size_t)bh * SEQ * DK;

    __shared__ __half kfs[2][64 * 64];
    __shared__ __half vs [2][64 * 64];

    const int tid = threadIdx.x;
    const int ty = tid >> 4, tx = tid & 15;

    auto issue = [&](int s, int c) {
        uint32_t dk = s2u(&kfs[s][0]);
        uint32_t dv = s2u(&vs [s][0]);
        #pragma unroll
        for (int i = 0; i < 2; i++) {
            int idx = tid + i * 256, row = idx >> 3, seg = idx & 7;
            uint32_t off = (uint32_t)(row * 128 + seg * 16);
            const __half* sk = kf + (size_t)(c + row) * 64 + seg * 8;
            const __half* sv = v  + (size_t)(c + row) * 64 + seg * 8;
            asm volatile("cp.async.cg.shared.global [%0], [%1], 16;" :: "r"(dk + off), "l"(sk));
            asm volatile("cp.async.cg.shared.global [%0], [%1], 16;" :: "r"(dv + off), "l"(sv));
        }
        asm volatile("cp.async.commit_group;");
    };

    float acc[4][4] = {{0}};
    float ks[4] = {0, 0, 0, 0};

    issue(0, 0);
    for (int cc = 0; cc < SEQ / 64; cc++) {
        const int buf = cc & 1;
        if (cc + 1 < SEQ / 64) {
            issue(buf ^ 1, (cc + 1) * 64);
            asm volatile("cp.async.wait_group 1;");
        } else {
            asm volatile("cp.async.wait_group 0;");
        }
        __syncthreads();

        #pragma unroll 4
        for (int n = 0; n < 64; n++) {
            const __half2* kr = (const __half2*)&kfs[buf][n * 64];
            const __half2* vr = (const __half2*)&vs [buf][n * 64];
            float2 ka = __half22float2(kr[ty * 2]);
            float2 kb = __half22float2(kr[ty * 2 + 1]);
            float2 va = __half22float2(vr[tx * 2]);
            float2 vb = __half22float2(vr[tx * 2 + 1]);
            float a[4] = {ka.x, ka.y, kb.x, kb.y};
            float b[4] = {va.x, va.y, vb.x, vb.y};
            #pragma unroll
            for (int i = 0; i < 4; i++)
                #pragma unroll
                for (int j = 0; j < 4; j++) acc[i][j] += a[i] * b[j];
            if (tx == 0) {
                #pragma unroll
                for (int i = 0; i < 4; i++) ks[i] += a[i];
            }
        }
        __syncthreads();
    }

    float* kvout = g_kv + (size_t)bh * DK * DK;
    const int d0 = ty * 4, e0 = tx * 4;
    #pragma unroll
    for (int i = 0; i < 4; i++) {
        float4 r = make_float4(acc[i][0], acc[i][1], acc[i][2], acc[i][3]);
        *(float4*)&kvout[(d0 + i) * DK + e0] = r;
    }
    if (tx == 0) {
        #pragma unroll
        for (int i = 0; i < 4; i++) g_ks[(size_t)bh * DK + d0 + i] = ks[i];
    }
}

// K3: readout; half qf -> half token-major [B,N,H,Dk]
__global__ __launch_bounds__(256) void attn_kernel()
{
    const int bh = blockIdx.x;
    const int b = bh >> 4, h = bh & 15;

    __shared__ float kvs[64 * 64];
    __shared__ float kss[64];

    const int tid = threadIdx.x;
    const float* kvg = g_kv + (size_t)bh * DK * DK;
    for (int i = tid; i < 64 * 64; i += 256) kvs[i] = kvg[i];
    if (tid < 64) kss[tid] = g_ks[(size_t)bh * DK + tid];
    __syncthreads();

    const int warp = tid >> 5, lane = tid & 31;
    const __half* qf = g_qfh + (size_t)bh * SEQ * DK;

    for (int n = warp; n < SEQ; n += 8) {
        const __half2* qr = (const __half2*)(qf + (size_t)n * 64);
        float a0 = 0.f, a1 = 0.f, den = 0.f;
        #pragma unroll
        for (int dd = 0; dd < 32; dd++) {
            float2 q2 = __half22float2(qr[dd]);       // broadcast load
            const int d = dd * 2;
            a0  += q2.x * kvs[d*64 + lane]        + q2.y * kvs[(d+1)*64 + lane];
            a1  += q2.x * kvs[d*64 + lane + 32]   + q2.y * kvs[(d+1)*64 + lane + 32];
            den += q2.x * kss[d]                  + q2.y * kss[d+1];
        }
        const float inv = 1.f / (den + EPSV);
        const size_t o = (((size_t)(b * SEQ + n)) * NH + h) * 64;
        g_ath[o + lane]      = __float2half_rn(a0 * inv);
        g_ath[o + lane + 32] = __float2half_rn(a1 * inv);
    }
}

// ---------------------------------------------------------------
extern "C" void kernel_launch(void* const* d_in, const int* in_sizes, int n_in,
                              void* d_out, int out_size)
{
    const float* x  = (const float*)d_in[0];
    const float* Wq = (const float*)d_in[1];
    const float* bq = (const float*)d_in[2];
    const float* Wk = (const float*)d_in[3];
    const float* bk = (const float*)d_in[4];
    const float* Wv = (const float*)d_in[5];
    const float* bv = (const float*)d_in[6];
    const float* Wo = (const float*)d_in[7];
    const float* bo = (const float*)d_in[8];
    float* out = (float*)d_out;

    cudaFuncSetAttribute(qkv_mma, cudaFuncAttributeMaxDynamicSharedMemorySize, SMEM_BYTES);
    cudaFuncSetAttribute(out_mma, cudaFuncAttributeMaxDynamicSharedMemorySize, SMEM_BYTES);

    cvt_x_kernel<<<(MTOK * DM / 4) / 256, 256>>>(x);
    transpose_w<<<dim3(DM/32, DM/32, 4), 256>>>(Wq, Wk, Wv, Wo);

    dim3 gq(DM / BN, MTOK / BM, 3);          // (8, 128, 3)
    qkv_mma<<<gq, 256, SMEM_BYTES>>>(bq, bk, bv);

    kv_kernel<<<BATCH * NH, 256>>>();
    attn_kernel<<<BATCH * NH, 256>>>();

    dim3 go(DM / BN, MTOK / BM);             // (8, 128)
    out_mma<<<go, 256, SMEM_BYTES>>>(bo, out);
}

// round 10
// speedup vs baseline: 7.7458x; 1.6134x over previous
#include <cuda_runtime.h>
#include <cuda_fp16.h>
#include <stdint.h>

#define DM    1024
#define NH    16
#define DK    64
#define BATCH 32
#define SEQ   512
#define MTOK  (BATCH*SEQ)   // 16384
#define EPSV  1e-6f

#define BM 128
#define BN 128
#define BK 64                        // halves per K chunk (128B row)
#define NCH (DM/BK)                  // 16
#define ROWB 144                     // padded row stride in bytes (128 + 16)
#define STAGE_BYTES ((BM+BN)*ROWB)   // 36864
#define SMEM_BYTES (3*STAGE_BYTES)   // 110592

// -------- scratch (static __device__, no runtime allocation) --------
__device__ __half g_xh[(size_t)MTOK * DM];       // half(x)
__device__ __half g_wth[4][(size_t)DM * DM];     // transposed half W{q,k,v,o}: [N,K]
__device__ __half g_qfh[(size_t)MTOK * DM];      // phi(Q) half, head-major [B,H,N,Dk]
__device__ __half g_kfh[(size_t)MTOK * DM];      // phi(K) half, head-major
__device__ __half g_vh [(size_t)MTOK * DM];      // V half, head-major
__device__ __half g_ath[(size_t)MTOK * DM];      // attn out half, token-major [B,N,H,Dk]
__device__ __half g_kvT[(size_t)BATCH * NH * DK * DK];  // kv^T [e][d], half
__device__ float  g_ks[(size_t)BATCH * NH * DK];

// ------------------------ helpers ------------------------
__device__ __forceinline__ uint32_t s2u(const void* p) {
    return (uint32_t)__cvta_generic_to_shared(p);
}
__device__ __forceinline__ void mma_f16(float* c, const uint32_t* a, const uint32_t* b) {
    asm volatile(
        "mma.sync.aligned.m16n8k16.row.col.f32.f16.f16.f32 "
        "{%0,%1,%2,%3},{%4,%5,%6,%7},{%8,%9},{%0,%1,%2,%3};"
        : "+f"(c[0]), "+f"(c[1]), "+f"(c[2]), "+f"(c[3])
        : "r"(a[0]), "r"(a[1]), "r"(a[2]), "r"(a[3]),
          "r"(b[0]), "r"(b[1]));
}
__device__ __forceinline__ void ldsm_x4(uint32_t& r0, uint32_t& r1, uint32_t& r2,
                                        uint32_t& r3, uint32_t addr) {
    asm volatile("ldmatrix.sync.aligned.m8n8.x4.shared.b16 {%0,%1,%2,%3}, [%4];"
                 : "=r"(r0), "=r"(r1), "=r"(r2), "=r"(r3) : "r"(addr));
}
__device__ __forceinline__ void ldsm_x4t(uint32_t& r0, uint32_t& r1, uint32_t& r2,
                                         uint32_t& r3, uint32_t addr) {
    asm volatile("ldmatrix.sync.aligned.m8n8.x4.trans.shared.b16 {%0,%1,%2,%3}, [%4];"
                 : "=r"(r0), "=r"(r1), "=r"(r2), "=r"(r3) : "r"(addr));
}

// ------------------------ fused fp16 GEMM body ------------------------
// A:[M,1024] half row-major; Bt:[N,1024] half row-major (W^T)
// mode 0: bias+phi -> half head-major; 1: bias -> half head-major; 2: bias -> fp32 row-major
__device__ __forceinline__ void gemm_body(
    const __half* __restrict__ A, const __half* __restrict__ Bt,
    const float* __restrict__ bias, float* __restrict__ dstf,
    __half* __restrict__ dsth, int m0, int n0, int mode)
{
    extern __shared__ char smc[];
    const uint32_t smb = s2u(smc);
    const int tid  = threadIdx.x;
    const int wid  = tid >> 5, lane = tid & 31;
    const int wm   = wid >> 2, wn   = wid & 3;   // 2 x 4 warp grid
    const int g    = lane >> 2, tig = lane & 3;

    float acc[4][4][4];
    #pragma unroll
    for (int mt = 0; mt < 4; mt++)
        #pragma unroll
        for (int nt = 0; nt < 4; nt++)
            #pragma unroll
            for (int q = 0; q < 4; q++) acc[mt][nt][q] = 0.f;

    const uint32_t aOff = (uint32_t)((lane & 15) * ROWB + (lane >> 4) * 16);
    const uint32_t bOff = (uint32_t)(((lane & 7) + ((lane >> 4) << 3)) * ROWB
                                     + ((lane >> 3) & 1) * 16);

    auto issue_load = [&](int s, int k0) {
        const uint32_t sb = smb + (uint32_t)s * STAGE_BYTES;
        #pragma unroll
        for (int i = 0; i < 4; i++) {                 // A rows 0..127
            int idx = tid + i * 256, row = idx >> 3, seg = idx & 7;
            const __half* src = A + (size_t)(m0 + row) * DM + k0 + seg * 8;
            asm volatile("cp.async.cg.shared.global [%0], [%1], 16;"
                         :: "r"(sb + (uint32_t)(row * ROWB + seg * 16)), "l"(src));
        }
        #pragma unroll
        for (int i = 4; i < 8; i++) {                 // B rows 128..255
            int idx = tid + i * 256, row = idx >> 3, seg = idx & 7;
            const __half* src = Bt + (size_t)(n0 + row - 128) * DM + k0 + seg * 8;
            asm volatile("cp.async.cg.shared.global [%0], [%1], 16;"
                         :: "r"(sb + (uint32_t)(row * ROWB + seg * 16)), "l"(src));
        }
        asm volatile("cp.async.commit_group;");
    };

    issue_load(0, 0);
    issue_load(1, BK);

    #pragma unroll 1
    for (int kc = 0; kc < NCH; kc++) {
        if (kc < NCH - 1) asm volatile("cp.async.wait_group 1;");
        else              asm volatile("cp.async.wait_group 0;");
        __syncthreads();

        if (kc + 2 < NCH) issue_load((kc + 2) % 3, (kc + 2) * BK);

        const uint32_t sb    = smb + (uint32_t)(kc % 3) * STAGE_BYTES;
        const uint32_t aWarp = sb + (uint32_t)(wm * 64) * ROWB + aOff;
        const uint32_t bWarp = sb + (uint32_t)(128 + wn * 32) * ROWB + bOff;

        #pragma unroll
        for (int kk = 0; kk < 4; kk++) {
            uint32_t a[4][4], b[4][2];
            #pragma unroll
            for (int mt = 0; mt < 4; mt++)
                ldsm_x4(a[mt][0], a[mt][1], a[mt][2], a[mt][3],
                        aWarp + (uint32_t)(mt * 16 * ROWB + kk * 32));
            ldsm_x4(b[0][0], b[0][1], b[1][0], b[1][1], bWarp + (uint32_t)(kk * 32));
            ldsm_x4(b[2][0], b[2][1], b[3][0], b[3][1],
                    bWarp + (uint32_t)(16 * ROWB + kk * 32));
            #pragma unroll
            for (int mt = 0; mt < 4; mt++)
                #pragma unroll
                for (int nt = 0; nt < 4; nt++)
                    mma_f16(acc[mt][nt], a[mt], b[nt]);
        }
    }

    const int mbase = m0 + wm * 64;
    const int nb    = n0 + wn * 32;
    #pragma unroll
    for (int mt = 0; mt < 4; mt++) {
        #pragma unroll
        for (int half = 0; half < 2; half++) {
            const int m = mbase + mt * 16 + g + half * 8;
            #pragma unroll
            for (int nt = 0; nt < 4; nt++) {
                const int c = nb + nt * 8 + 2 * tig;
                float v0 = acc[mt][nt][half * 2 + 0] + bias[c];
                float v1 = acc[mt][nt][half * 2 + 1] + bias[c + 1];
                if (mode == 0) {
                    v0 = (v0 > 0.f) ? (v0 + 1.f) : __expf(v0);
                    v1 = (v1 > 0.f) ? (v1 + 1.f) : __expf(v1);
                }
                if (mode == 2) {
                    *(float2*)&dstf[(size_t)m * DM + c] = make_float2(v0, v1);
                } else {
                    const int b = m >> 9, n = m & 511;
                    const int h = c >> 6, d = c & 63;
                    *(__half2*)&dsth[((((size_t)(b * NH + h)) * SEQ + n) << 6) + d] =
                        __floats2half2_rn(v0, v1);
                }
            }
        }
    }
}

// ------------------------ kernels ------------------------
__global__ __launch_bounds__(256) void qkv_mma(
    const float* __restrict__ bq, const float* __restrict__ bk, const float* __restrict__ bv)
{
    const int z = blockIdx.z;
    const float* bias = (z == 0) ? bq : (z == 1) ? bk : bv;
    __half* dst       = (z == 0) ? g_qfh : (z == 1) ? g_kfh : g_vh;
    gemm_body(g_xh, g_wth[z], bias, nullptr, dst,
              blockIdx.y * BM, blockIdx.x * BN, (z < 2) ? 0 : 1);
}

__global__ __launch_bounds__(256) void out_mma(
    const float* __restrict__ bo, float* __restrict__ out)
{
    gemm_body(g_ath, g_wth[3], bo, out, nullptr, blockIdx.y * BM, blockIdx.x * BN, 2);
}

__global__ __launch_bounds__(256) void cvt_x_kernel(const float* __restrict__ x)
{
    int idx = blockIdx.x * 256 + threadIdx.x;
    float4 v = ((const float4*)x)[idx];
    ((__half2*)g_xh)[idx * 2 + 0] = __floats2half2_rn(v.x, v.y);
    ((__half2*)g_xh)[idx * 2 + 1] = __floats2half2_rn(v.z, v.w);
}

__global__ __launch_bounds__(256) void transpose_w(
    const float* __restrict__ Wq, const float* __restrict__ Wk,
    const float* __restrict__ Wv, const float* __restrict__ Wo)
{
    const int z = blockIdx.z;
    const float* W = (z == 0) ? Wq : (z == 1) ? Wk : (z == 2) ? Wv : Wo;
    __half* dst = g_wth[z];
    __shared__ float t[32][33];
    const int k0 = blockIdx.x * 32, n0 = blockIdx.y * 32;
    const int tx = threadIdx.x & 31, ty = threadIdx.x >> 5;
    #pragma unroll
    for (int i = 0; i < 4; i++)
        t[ty + i*8][tx] = W[(size_t)(k0 + ty + i*8) * DM + n0 + tx];
    __syncthreads();
    #pragma unroll
    for (int i = 0; i < 4; i++)
        dst[(size_t)(n0 + ty + i*8) * DM + k0 + tx] = __float2half_rn(t[tx][ty + i*8]);
}

// K2: kv^T[e][d] = sum_n kf[n][d]*v[n][e] via HMMA (trans ldmatrix); fused ksum.
// 128 threads (4 warps), grid 512.
#define KVROW 72   // padded row stride in halves (144B)
__global__ __launch_bounds__(128) void kv_kernel()
{
    const int bh = blockIdx.x;
    const __half* kf = g_kfh + (size_t)bh * SEQ * DK;
    const __half* v  = g_vh  + (size_t)bh * SEQ * DK;

    __shared__ __half kfs[2][64 * KVROW];
    __shared__ __half vs [2][64 * KVROW];

    const int tid  = threadIdx.x;
    const int wid  = tid >> 5, lane = tid & 31;
    const int wm   = wid >> 1, wn = wid & 1;       // 2x2 warp grid
    const int d_base = wm * 32, e_base = wn * 32;
    const int g8   = lane >> 3, r8 = lane & 7;
    const int g    = lane >> 2, tig = lane & 3;

    // trans-ldmatrix per-lane offsets (bytes)
    const uint32_t aTO = (uint32_t)((((g8 >> 1) * 8) + r8) * 2 * KVROW + ((g8 & 1) * 8) * 2);
    const uint32_t bTO = (uint32_t)((((g8 & 1) * 8) + r8) * 2 * KVROW + ((g8 >> 1) * 8) * 2);

    auto issue = [&](int s, int c) {
        uint32_t dk = s2u(&kfs[s][0]);
        uint32_t dv = s2u(&vs [s][0]);
        #pragma unroll
        for (int i = 0; i < 4; i++) {
            int idx = tid + i * 128, row = idx >> 3, seg = idx & 7;
            uint32_t off = (uint32_t)(row * (KVROW * 2) + seg * 16);
            const __half* sk = kf + (size_t)(c + row) * 64 + seg * 8;
            const __half* sv = v  + (size_t)(c + row) * 64 + seg * 8;
            asm volatile("cp.async.cg.shared.global [%0], [%1], 16;" :: "r"(dk + off), "l"(sk));
            asm volatile("cp.async.cg.shared.global [%0], [%1], 16;" :: "r"(dv + off), "l"(sv));
        }
        asm volatile("cp.async.commit_group;");
    };

    float acc[2][4][4];
    #pragma unroll
    for (int mt = 0; mt < 2; mt++)
        #pragma unroll
        for (int nt = 0; nt < 4; nt++)
            #pragma unroll
            for (int q = 0; q < 4; q++) acc[mt][nt][q] = 0.f;
    float ks = 0.f;                                  // tid<64: ksum[d=tid]

    issue(0, 0);
    for (int cc = 0; cc < SEQ / 64; cc++) {
        const int buf = cc & 1;
        if (cc + 1 < SEQ / 64) {
            issue(buf ^ 1, (cc + 1) * 64);
            asm volatile("cp.async.wait_group 1;");
        } else {
            asm volatile("cp.async.wait_group 0;");
        }
        __syncthreads();

        const uint32_t kb = s2u(&kfs[buf][0]);
        const uint32_t vb = s2u(&vs [buf][0]);

        #pragma unroll
        for (int kk = 0; kk < 4; kk++) {             // n_seq chunks of 16
            const uint32_t nb0 = (uint32_t)(kk * 16) * (KVROW * 2);
            uint32_t a[2][4], b[4][2];
            #pragma unroll
            for (int mt = 0; mt < 2; mt++)
                ldsm_x4t(a[mt][0], a[mt][1], a[mt][2], a[mt][3],
                         kb + nb0 + (uint32_t)(d_base + mt * 16) * 2 + aTO);
            #pragma unroll
            for (int p = 0; p < 2; p++) {
                uint32_t addr = vb + nb0 + (uint32_t)(e_base + p * 16) * 2 + bTO;
                ldsm_x4t(b[p*2][0], b[p*2][1], b[p*2+1][0], b[p*2+1][1], addr);
            }
            #pragma unroll
            for (int mt = 0; mt < 2; mt++)
                #pragma unroll
                for (int nt = 0; nt < 4; nt++)
                    mma_f16(acc[mt][nt], a[mt], b[nt]);
        }

        if (tid < 64) {
            #pragma unroll 8
            for (int n = 0; n < 64; n++)
                ks += __half2float(kfs[buf][n * KVROW + tid]);
        }
        __syncthreads();
    }

    // store kv^T[e][d] as half
    __half* kvt = g_kvT + (size_t)bh * DK * DK;
    #pragma unroll
    for (int mt = 0; mt < 2; mt++) {
        #pragma unroll
        for (int half = 0; half < 2; half++) {
            const int d = d_base + mt * 16 + g + half * 8;
            #pragma unroll
            for (int nt = 0; nt < 4; nt++) {
                const int e = e_base + nt * 8 + 2 * tig;
                kvt[(size_t)e * DK + d]       = __float2half_rn(acc[mt][nt][half*2+0]);
                kvt[(size_t)(e+1) * DK + d]   = __float2half_rn(acc[mt][nt][half*2+1]);
            }
        }
    }
    if (tid < 64) g_ks[(size_t)bh * DK + tid] = ks;
}

// K3: out = qf @ kv / den via HMMA. 256 threads (8 warps), grid 512.
#define AT_QBYTES (SEQ * KVROW * 2)        // 73728
#define AT_KVOFF  AT_QBYTES
#define AT_KSOFF  (AT_KVOFF + 64 * KVROW * 2)   // + 9216 = 82944
#define AT_DENOFF (AT_KSOFF + 64 * 4)           // 83200
#define AT_SMEM   (AT_DENOFF + SEQ * 4)         // 85248
__global__ __launch_bounds__(256) void attn_kernel()
{
    const int bh = blockIdx.x;
    const int b = bh >> 4, h = bh & 15;

    extern __shared__ char smc[];
    __half* qfs = (__half*)smc;
    __half* kvs = (__half*)(smc + AT_KVOFF);
    float*  kss = (float*)(smc + AT_KSOFF);
    float*  den = (float*)(smc + AT_DENOFF);
    const uint32_t smb = s2u(smc);

    const int tid  = threadIdx.x;
    const int wid  = tid >> 5, lane = tid & 31;
    const int g    = lane >> 2, tig = lane & 3;

    const __half* qf  = g_qfh + (size_t)bh * SEQ * DK;
    const __half* kvt = g_kvT + (size_t)bh * DK * DK;

    // load qf (512x64) and kvT (64x64) into padded SMEM
    {
        uint32_t dq = smb;
        #pragma unroll
        for (int i = 0; i < 16; i++) {
            int idx = tid + i * 256, row = idx >> 3, seg = idx & 7;
            const __half* src = qf + (size_t)row * 64 + seg * 8;
            asm volatile("cp.async.cg.shared.global [%0], [%1], 16;"
                         :: "r"(dq + (uint32_t)(row * (KVROW*2) + seg * 16)), "l"(src));
        }
        uint32_t dk = smb + AT_KVOFF;
        #pragma unroll
        for (int i = 0; i < 2; i++) {
            int idx = tid + i * 256, row = idx >> 3, seg = idx & 7;
            const __half* src = kvt + (size_t)row * 64 + seg * 8;
            asm volatile("cp.async.cg.shared.global [%0], [%1], 16;"
                         :: "r"(dk + (uint32_t)(row * (KVROW*2) + seg * 16)), "l"(src));
        }
        asm volatile("cp.async.commit_group;");
    }
    if (tid < 64) kss[tid] = g_ks[(size_t)bh * DK + tid];
    asm volatile("cp.async.wait_group 0;");
    __syncthreads();

    // denominators: rows tid and tid+256
    #pragma unroll
    for (int rr = 0; rr < 2; rr++) {
        const int n = tid + rr * 256;
        const __half* qr = qfs + (size_t)n * KVROW;
        float dsum = 0.f;
        #pragma unroll 16
        for (int d = 0; d < 64; d++) dsum += __half2float(qr[d]) * kss[d];
        den[n] = 1.f / (dsum + EPSV);
    }
    __syncthreads();

    const uint32_t aOff = (uint32_t)((lane & 15) * (KVROW*2) + (lane >> 4) * 16);
    const uint32_t bOff = (uint32_t)(((lane & 7) + ((lane >> 4) << 3)) * (KVROW*2)
                                     + ((lane >> 3) & 1) * 16);
    const int m_base = wid * 64;
    const uint32_t aWarp = smb + (uint32_t)m_base * (KVROW*2) + aOff;
    const uint32_t bWarp = smb + AT_KVOFF + bOff;

    __half* outp = g_ath;
    #pragma unroll
    for (int nh = 0; nh < 2; nh++) {                  // e halves 0-31 / 32-63
        float acc[4][4][4];
        #pragma unroll
        for (int mt = 0; mt < 4; mt++)
            #pragma unroll
            for (int nt = 0; nt < 4; nt++)
                #pragma unroll
                for (int q = 0; q < 4; q++) acc[mt][nt][q] = 0.f;

        #pragma unroll
        for (int kk = 0; kk < 4; kk++) {              // d chunks of 16
            uint32_t a[4][4], b[4][2];
            #pragma unroll
            for (int mt = 0; mt < 4; mt++)
                ldsm_x4(a[mt][0], a[mt][1], a[mt][2], a[mt][3],
                        aWarp + (uint32_t)(mt * 16 * (KVROW*2) + kk * 32));
            ldsm_x4(b[0][0], b[0][1], b[1][0], b[1][1],
                    bWarp + (uint32_t)((nh * 32) * (KVROW*2) + kk * 32));
            ldsm_x4(b[2][0], b[2][1], b[3][0], b[3][1],
                    bWarp + (uint32_t)((nh * 32 + 16) * (KVROW*2) + kk * 32));
            #pragma unroll
            for (int mt = 0; mt < 4; mt++)
                #pragma unroll
                for (int nt = 0; nt < 4; nt++)
                    mma_f16(acc[mt][nt], a[mt], b[nt]);
        }

        #pragma unroll
        for (int mt = 0; mt < 4; mt++) {
            #pragma unroll
            for (int half = 0; half < 2; half++) {
                const int m = m_base + mt * 16 + g + half * 8;   // token row
                const float inv = den[m];
                const size_t o = (((size_t)(b * SEQ + m)) * NH + h) * 64;
                #pragma unroll
                for (int nt = 0; nt < 4; nt++) {
                    const int e = nh * 32 + nt * 8 + 2 * tig;
                    *(__half2*)&outp[o + e] = __floats2half2_rn(
                        acc[mt][nt][half*2+0] * inv, acc[mt][nt][half*2+1] * inv);
                }
            }
        }
    }
}

// ---------------------------------------------------------------
extern "C" void kernel_launch(void* const* d_in, const int* in_sizes, int n_in,
                              void* d_out, int out_size)
{
    const float* x  = (const float*)d_in[0];
    const float* Wq = (const float*)d_in[1];
    const float* bq = (const float*)d_in[2];
    const float* Wk = (const float*)d_in[3];
    const float* bk = (const float*)d_in[4];
    const float* Wv = (const float*)d_in[5];
    const float* bv = (const float*)d_in[6];
    const float* Wo = (const float*)d_in[7];
    const float* bo = (const float*)d_in[8];
    float* out = (float*)d_out;

    cudaFuncSetAttribute(qkv_mma, cudaFuncAttributeMaxDynamicSharedMemorySize, SMEM_BYTES);
    cudaFuncSetAttribute(out_mma, cudaFuncAttributeMaxDynamicSharedMemorySize, SMEM_BYTES);
    cudaFuncSetAttribute(attn_kernel, cudaFuncAttributeMaxDynamicSharedMemorySize, AT_SMEM);

    cvt_x_kernel<<<(MTOK * DM / 4) / 256, 256>>>(x);
    transpose_w<<<dim3(DM/32, DM/32, 4), 256>>>(Wq, Wk, Wv, Wo);

    dim3 gq(DM / BN, MTOK / BM, 3);          // (8, 128, 3)
    qkv_mma<<<gq, 256, SMEM_BYTES>>>(bq, bk, bv);

    kv_kernel<<<BATCH * NH, 128>>>();
    attn_kernel<<<BATCH * NH, 256, AT_SMEM>>>();

    dim3 go(DM / BN, MTOK / BM);             // (8, 128)
    out_mma<<<go, 256, SMEM_BYTES>>>(bo, out);
}